// round 8
// baseline (speedup 1.0000x reference)
#include <cuda_runtime.h>
#include <cstdint>

// Problem constants
#define BATCH 64
#define SEQT  512
#define IN    512
#define HID   1024
#define G4    4096
#define KTOT  1536
#define OUTD  512

#define NBLK  128           // persistent grid, 1 CTA/SM
#define NTHR  256           // 8 warps
#define K8TOT 192           // total k8 (x: 0..63, h: 64..191)
#define K8X   64
#define K8H   128
#define KSL   32            // k8 per warp K-slice in the recurrent loop (128/4)

// smem: W fragment-packed (resident) + 8 partial tiles (32x32, pitch 33)
#define WF_FLOATS (K8TOT * 4 * 32 * 2)     // 49152 floats = 196608 B
#define P_PITCH   33
#define P_TILE    (32 * P_PITCH)
#define SMEM_TOTAL ((WF_FLOATS + 8 * P_TILE) * 4)   // 230400 B

// ---- device-global scratch ----
__device__ float    d_W[(size_t)G4 * KTOT];              // tf32-rounded, packed cols
__device__ float    d_bias[G4];
__device__ float    d_xfrag[(size_t)SEQT * K8X * 4 * 32 * 4]; // x in fragment order
__device__ float    d_gx[(size_t)SEQT * BATCH * G4];     // precomputed x-gate proj (512MB)
__device__ float    d_hfrag[2 * K8H * 4 * 32 * 4];       // h in fragment order, dbl-buf
__device__ float    d_hfin[BATCH * HID];
__device__ unsigned d_bar_grp[8 * 64];                   // spread group counters
__device__ unsigned d_bar_root;

// ============================ helpers =======================================
__device__ __forceinline__ float tf32r(float v) {
    uint32_t r;
    asm("cvt.rna.tf32.f32 %0, %1;" : "=r"(r) : "f"(v));
    return __uint_as_float(r);
}
__device__ __forceinline__ void mma_tf32(float c[4], const uint32_t a[4],
                                         const uint32_t b[2]) {
    asm volatile(
        "mma.sync.aligned.m16n8k8.row.col.f32.tf32.tf32.f32 "
        "{%0,%1,%2,%3}, {%4,%5,%6,%7}, {%8,%9}, {%0,%1,%2,%3};"
        : "+f"(c[0]), "+f"(c[1]), "+f"(c[2]), "+f"(c[3])
        : "r"(a[0]), "r"(a[1]), "r"(a[2]), "r"(a[3]), "r"(b[0]), "r"(b[1]));
}
__device__ __forceinline__ float sigf(float v)     { return 1.f / (1.f + __expf(-v)); }
__device__ __forceinline__ float tanhfast(float v) { return 2.f / (1.f + __expf(-2.f * v)) - 1.f; }

// ============================ prep kernel ===================================
// Packed W column j: gate g=(j>>3)&3 (f,i,c,o), unit=(j>>5)*8+(j&7).
// x fragments: [t][k8][mt][lane][reg]; b = mt*16+(lane>>2)+8*(reg&1),
//              k = k8*8+(lane&3)+4*(reg>>1)
__global__ void prep_kernel(
    const float* __restrict__ x,
    const float* __restrict__ Wxf, const float* __restrict__ Whf, const float* __restrict__ bhf,
    const float* __restrict__ Wxi, const float* __restrict__ Whi, const float* __restrict__ bhi,
    const float* __restrict__ Wxc, const float* __restrict__ Whc, const float* __restrict__ bhc,
    const float* __restrict__ Wxo, const float* __restrict__ Who, const float* __restrict__ bho)
{
    const float* Wx[4] = {Wxf, Wxi, Wxc, Wxo};
    const float* Wh[4] = {Whf, Whi, Whc, Who};
    const float* bh[4] = {bhf, bhi, bhc, bho};

    size_t gid = (size_t)blockIdx.x * blockDim.x + threadIdx.x;
    size_t str = (size_t)gridDim.x * blockDim.x;

    for (size_t i = gid; i < (size_t)G4 * KTOT; i += str) {
        int j = (int)(i / KTOT), k = (int)(i % KTOT);
        int g = (j >> 3) & 3;
        int r = (j >> 5) * 8 + (j & 7);
        float v = (k < IN) ? Wx[g][(size_t)r * IN + k]
                           : Wh[g][(size_t)r * HID + (k - IN)];
        d_W[i] = tf32r(v);
    }
    for (size_t i = gid; i < (size_t)G4; i += str) {
        int g = (int)((i >> 3) & 3);
        int r = (int)((i >> 5) * 8 + (i & 7));
        d_bias[i] = bh[g][r];
    }
    for (size_t i = gid; i < (size_t)SEQT * K8X * 4 * 32 * 4; i += str) {
        int r    = (int)(i & 3);
        int lane = (int)((i >> 2) & 31);
        int mt   = (int)((i >> 7) & 3);
        int k8   = (int)((i >> 9) & 63);
        int t    = (int)(i >> 15);
        int b = mt * 16 + (lane >> 2) + 8 * (r & 1);
        int k = k8 * 8 + (lane & 3) + 4 * (r >> 1);
        d_xfrag[i] = tf32r(x[((size_t)b * SEQT + t) * IN + k]);
    }
    for (size_t i = gid; i < (size_t)2 * K8H * 4 * 32 * 4; i += str)
        d_hfrag[i] = 0.f;
    for (size_t i = gid; i < 8 * 64; i += str) d_bar_grp[i] = 0u;
    if (gid == 0) d_bar_root = 0u;
}

// ============================ two-level grid barrier ========================
__device__ __forceinline__ void grid_bar(int t, int blk)
{
    __syncthreads();
    if (threadIdx.x == 0) {
        __threadfence();
        const unsigned g = (unsigned)(blk >> 4);              // 8 groups of 16
        unsigned v = atomicAdd(&d_bar_grp[g * 64], 1u) + 1u;
        if (v == 16u * (unsigned)(t + 1))
            atomicAdd(&d_bar_root, 1u);
        while (*(volatile unsigned*)&d_bar_root < 8u * (unsigned)(t + 1))
            __nanosleep(32);
        __threadfence();
    }
    __syncthreads();
}

// h-fragment load (recurrent loop): k8 in 0..127
__device__ __forceinline__ uint4 ldH(int rbuf, int k8, int mt, int lane)
{
    size_t off = (((size_t)(rbuf * K8H + k8) * 4 + mt) * 32 + lane) * 4;
    return __ldcg((const uint4*)&d_hfrag[off]);
}
// x-fragment load (pre-phase): k8 in 0..63
__device__ __forceinline__ uint4 ldX(int t, int k8, int mt, int lane)
{
    size_t off = ((((size_t)t * K8X + k8) * 4 + mt) * 32 + lane) * 4;
    return __ldg((const uint4*)&d_xfrag[off]);
}

// ============================ main persistent kernel ========================
__global__ void __launch_bounds__(NTHR, 1) lstm_kernel(
    const float* __restrict__ Wout,
    const float* __restrict__ bout,
    float* __restrict__ out)
{
    extern __shared__ float smf[];
    float* Wf = smf;
    float* P  = smf + WF_FLOATS;

    const int tid  = threadIdx.x;
    const int wid  = tid >> 5;
    const int lane = tid & 31;
    const int g8   = lane >> 2;
    const int ql   = lane & 3;
    const int blk  = blockIdx.x;

    // ---- one-time: pack this CTA's W columns into fragment order ----
    for (int j = tid; j < K8TOT * 4 * 32; j += NTHR) {
        int k8 = j >> 7, nt = (j >> 5) & 3, ln = j & 31;
        size_t col = (size_t)(blk * 32 + nt * 8 + (ln >> 2));
        int k = k8 * 8 + (ln & 3);
        Wf[j * 2 + 0] = __ldg(&d_W[col * KTOT + k]);
        Wf[j * 2 + 1] = __ldg(&d_W[col * KTOT + k + 4]);
    }
    __syncthreads();

    // ================= PRE-PHASE: gx = x @ Wx^T for all t ==================
    // Each warp owns timesteps t = wid, wid+8, ...; full K=512; no syncs.
    for (int t = wid; t < SEQT; t += 8) {
        float acc[4][4][4];
#pragma unroll
        for (int mt = 0; mt < 4; mt++)
#pragma unroll
            for (int nt = 0; nt < 4; nt++)
#pragma unroll
                for (int c = 0; c < 4; c++) acc[mt][nt][c] = 0.f;

        uint4 apf[2][4];
#pragma unroll
        for (int d = 0; d < 2; d++)
#pragma unroll
            for (int mt = 0; mt < 4; mt++)
                apf[d][mt] = ldX(t, d, mt, lane);

#pragma unroll 2
        for (int j = 0; j < K8X; j++) {
            const int slot = j & 1;
            uint32_t bfr[4][2];
#pragma unroll
            for (int nt = 0; nt < 4; nt++) {
                float2 bv = *(const float2*)&Wf[((j * 4) + nt) * 64 + lane * 2];
                bfr[nt][0] = __float_as_uint(bv.x);
                bfr[nt][1] = __float_as_uint(bv.y);
            }
#pragma unroll
            for (int mt = 0; mt < 4; mt++)
#pragma unroll
                for (int nt = 0; nt < 4; nt++)
                    mma_tf32(acc[mt][nt], (const uint32_t*)&apf[slot][mt], bfr[nt]);
            if (j + 2 < K8X) {
#pragma unroll
                for (int mt = 0; mt < 4; mt++)
                    apf[slot][mt] = ldX(t, j + 2, mt, lane);
            }
        }

        // write gx[t][b][blk*32 + jl] (float2: adjacent cols c&1)
#pragma unroll
        for (int mt = 0; mt < 4; mt++)
#pragma unroll
            for (int nt = 0; nt < 4; nt++)
#pragma unroll
                for (int ch = 0; ch < 2; ch++) {
                    int row = mt * 16 + g8 + 8 * ch;
                    int jl  = nt * 8 + 2 * ql;
                    __stcg((float2*)&d_gx[((size_t)t * BATCH + row) * G4 + blk * 32 + jl],
                           make_float2(acc[mt][nt][2 * ch], acc[mt][nt][2 * ch + 1]));
                }
    }
    __threadfence();
    __syncthreads();   // own CTA reads its own gx; order writes before loop

    // ================= RECURRENT LOOP (K = 1024, h only) ====================
    const int kslice = wid >> 1;          // 0..3
    const int mhalf  = wid & 1;           // batch half
    const int k8base = kslice * KSL;      // in h-space 0..127
    const int mbase  = mhalf * 2;

    const int b0p = tid >> 3,          u0p = tid & 7;
    const int b1p = (tid + 256) >> 3,  u1p = (tid + 256) & 7;
    float cst0 = 0.f, cst1 = 0.f;
    float bias0[4], bias1[4];
#pragma unroll
    for (int g = 0; g < 4; g++) {
        bias0[g] = __ldg(&d_bias[blk * 32 + g * 8 + u0p]);
        bias1[g] = __ldg(&d_bias[blk * 32 + g * 8 + u1p]);
    }

    for (int t = 0; t < SEQT; t++) {
        const int rbuf = t & 1, wbuf = rbuf ^ 1;

        // prefetch this thread's gx values (consumed in epilogue)
        float gx0[4], gx1[4];
#pragma unroll
        for (int g = 0; g < 4; g++) {
            gx0[g] = __ldcg(&d_gx[((size_t)t * BATCH + b0p) * G4 + blk * 32 + g * 8 + u0p]);
            gx1[g] = __ldcg(&d_gx[((size_t)t * BATCH + b1p) * G4 + blk * 32 + g * 8 + u1p]);
        }

        // -------- MMA phase: M=32 x N=32, K=256 per warp, no syncs ---------
        float acc[2][4][4];
#pragma unroll
        for (int m2 = 0; m2 < 2; m2++)
#pragma unroll
            for (int nt = 0; nt < 4; nt++)
#pragma unroll
                for (int c = 0; c < 4; c++) acc[m2][nt][c] = 0.f;

        uint4 apf[3][2];
#pragma unroll
        for (int d = 0; d < 3; d++)
#pragma unroll
            for (int m2 = 0; m2 < 2; m2++)
                apf[d][m2] = ldH(rbuf, k8base + d, mbase + m2, lane);

#pragma unroll 4
        for (int j = 0; j < KSL; j++) {
            const int slot = j % 3;
            uint32_t bfr[4][2];
#pragma unroll
            for (int nt = 0; nt < 4; nt++) {
                float2 bv = *(const float2*)
                    &Wf[(((K8X + k8base + j) * 4) + nt) * 64 + lane * 2];
                bfr[nt][0] = __float_as_uint(bv.x);
                bfr[nt][1] = __float_as_uint(bv.y);
            }
#pragma unroll
            for (int m2 = 0; m2 < 2; m2++)
#pragma unroll
                for (int nt = 0; nt < 4; nt++)
                    mma_tf32(acc[m2][nt], (const uint32_t*)&apf[slot][m2], bfr[nt]);
            if (j + 3 < KSL) {
#pragma unroll
                for (int m2 = 0; m2 < 2; m2++)
                    apf[slot][m2] = ldH(rbuf, k8base + j + 3, mbase + m2, lane);
            }
        }

        // -------- write partials --------
        float* Pw = P + wid * P_TILE;
#pragma unroll
        for (int m2 = 0; m2 < 2; m2++)
#pragma unroll
            for (int nt = 0; nt < 4; nt++)
#pragma unroll
                for (int c = 0; c < 4; c++) {
                    int row = m2 * 16 + g8 + 8 * (c >> 1);
                    int col = nt * 8 + 2 * ql + (c & 1);
                    Pw[row * P_PITCH + col] = acc[m2][nt][c];
                }
        __syncthreads();

        // -------- reduction + gate fusion --------
        {
            const int mh = b0p >> 5, r = b0p & 31;
            float pa[4];
#pragma unroll
            for (int g = 0; g < 4; g++) {
                float s = bias0[g] + gx0[g];
#pragma unroll
                for (int ks = 0; ks < 4; ks++)
                    s += P[(ks * 2 + mh) * P_TILE + r * P_PITCH + g * 8 + u0p];
                pa[g] = s;
            }
            float f = sigf(pa[0]), ig = sigf(pa[1]);
            float ch = tanhfast(pa[2]), o = sigf(pa[3]);
            cst0 = f * cst0 + ig * ch;
            float hv = tf32r(o * tanhfast(cst0));
            int ug = blk * 8 + u0p;
            if (t < SEQT - 1) {
                int hidx = ug >> 3;
                int mtw  = b0p >> 4;
                int lw   = (b0p & 7) * 4 + (ug & 3);
                int rw   = 2 * ((ug >> 2) & 1) + ((b0p >> 3) & 1);
                __stcg(&d_hfrag[(((size_t)(wbuf * K8H + hidx) * 4 + mtw) * 32 + lw) * 4 + rw], hv);
            } else {
                d_hfin[b0p * HID + ug] = hv;
            }
        }
        {
            const int mh = b1p >> 5, r = b1p & 31;
            float pa[4];
#pragma unroll
            for (int g = 0; g < 4; g++) {
                float s = bias1[g] + gx1[g];
#pragma unroll
                for (int ks = 0; ks < 4; ks++)
                    s += P[(ks * 2 + mh) * P_TILE + r * P_PITCH + g * 8 + u1p];
                pa[g] = s;
            }
            float f = sigf(pa[0]), ig = sigf(pa[1]);
            float ch = tanhfast(pa[2]), o = sigf(pa[3]);
            cst1 = f * cst1 + ig * ch;
            float hv = tf32r(o * tanhfast(cst1));
            int ug = blk * 8 + u1p;
            if (t < SEQT - 1) {
                int hidx = ug >> 3;
                int mtw  = b1p >> 4;
                int lw   = (b1p & 7) * 4 + (ug & 3);
                int rw   = 2 * ((ug >> 2) & 1) + ((b1p >> 3) & 1);
                __stcg(&d_hfrag[(((size_t)(wbuf * K8H + hidx) * 4 + mtw) * 32 + lw) * 4 + rw], hv);
            } else {
                d_hfin[b1p * HID + ug] = hv;
            }
        }

        grid_bar(t, blk);
    }

    // ---- tail: out[b][o] = h_final[b] . Wout[o] + bout[o]
    {
        const int gtid = blk * NTHR + tid;
        const int b = gtid & 63, o = gtid >> 6;
        const float4* hr = (const float4*)&d_hfin[(size_t)b * HID];
        const float4* wr = (const float4*)(Wout + ((size_t)o << 10));
        float s = __ldg(&bout[o]);
#pragma unroll 4
        for (int k = 0; k < HID / 4; k++) {
            float4 h4 = __ldcg(hr + k);
            float4 w4 = __ldg(wr + k);
            s += h4.x * w4.x + h4.y * w4.y + h4.z * w4.z + h4.w * w4.w;
        }
        out[(size_t)b * OUTD + o] = s;
    }
}

// ============================================================================
extern "C" void kernel_launch(void* const* d_in, const int* in_sizes, int n_in,
                              void* d_out, int out_size)
{
    (void)in_sizes; (void)n_in; (void)out_size;
    const float* x    = (const float*)d_in[0];
    const float* Wxf  = (const float*)d_in[1];
    const float* Whf  = (const float*)d_in[2];
    const float* bhf  = (const float*)d_in[3];
    const float* Wxi  = (const float*)d_in[4];
    const float* Whi  = (const float*)d_in[5];
    const float* bhi  = (const float*)d_in[6];
    const float* Wxc  = (const float*)d_in[7];
    const float* Whc  = (const float*)d_in[8];
    const float* bhc  = (const float*)d_in[9];
    const float* Wxo  = (const float*)d_in[10];
    const float* Who  = (const float*)d_in[11];
    const float* bho  = (const float*)d_in[12];
    const float* Wout = (const float*)d_in[13];
    const float* bout = (const float*)d_in[14];
    float* out = (float*)d_out;

    cudaFuncSetAttribute(lstm_kernel,
                         cudaFuncAttributeMaxDynamicSharedMemorySize, SMEM_TOTAL);

    prep_kernel<<<2048, 256>>>(x, Wxf, Whf, bhf, Wxi, Whi, bhi,
                               Wxc, Whc, bhc, Wxo, Who, bho);
    lstm_kernel<<<NBLK, NTHR, SMEM_TOTAL>>>(Wout, bout, out);
}

// round 9
// speedup vs baseline: 1.7109x; 1.7109x over previous
#include <cuda_runtime.h>
#include <cstdint>

// Problem constants
#define BATCH 64
#define SEQT  512
#define IN    512
#define HID   1024
#define G4    4096
#define KTOT  1536
#define OUTD  512

#define NBLK  128           // persistent grid, 1 CTA/SM
#define NTHR  512           // 16 warps = (kslice 0..7) x (mhalf 0..1)
#define K8TOT 192           // total k8 (x: 0..63, h: 64..191)
#define K8X   64
#define KSL   24            // k8 per warp K-slice (192/8)

// smem: W fragment-packed (resident) + 8 merged partial tiles (32x32, pitch 33)
#define WF_FLOATS (K8TOT * 4 * 32 * 2)     // 49152 floats = 196608 B
#define P_PITCH   33
#define P_TILE    (32 * P_PITCH)
#define SMEM_TOTAL ((WF_FLOATS + 8 * P_TILE) * 4)   // 230400 B

// ---- device-global scratch ----
__device__ float    d_W[(size_t)G4 * KTOT];              // tf32-rounded, packed cols
__device__ float    d_bias[G4];
__device__ float    d_xfrag[(size_t)SEQT * K8X * 4 * 32 * 4]; // x in fragment order
__device__ float    d_hfrag[2 * 128 * 4 * 32 * 4];       // h in fragment order, dbl-buf
__device__ float    d_hfin[BATCH * HID];
__device__ unsigned d_bar_grp[8 * 64];                   // spread group counters
__device__ unsigned d_bar_root;

// ============================ helpers =======================================
__device__ __forceinline__ float tf32r(float v) {
    uint32_t r;
    asm("cvt.rna.tf32.f32 %0, %1;" : "=r"(r) : "f"(v));
    return __uint_as_float(r);
}
__device__ __forceinline__ void mma_tf32(float c[4], const uint32_t a[4],
                                         const uint32_t b[2]) {
    asm volatile(
        "mma.sync.aligned.m16n8k8.row.col.f32.tf32.tf32.f32 "
        "{%0,%1,%2,%3}, {%4,%5,%6,%7}, {%8,%9}, {%0,%1,%2,%3};"
        : "+f"(c[0]), "+f"(c[1]), "+f"(c[2]), "+f"(c[3])
        : "r"(a[0]), "r"(a[1]), "r"(a[2]), "r"(a[3]), "r"(b[0]), "r"(b[1]));
}
__device__ __forceinline__ float sigf(float v)     { return 1.f / (1.f + __expf(-v)); }
__device__ __forceinline__ float tanhfast(float v) { return 2.f / (1.f + __expf(-2.f * v)) - 1.f; }

// ============================ prep kernel ===================================
// Packed W column j: gate g=(j>>3)&3 (f,i,c,o), unit=(j>>5)*8+(j&7).
// x fragments: [t][k8][mt][lane][reg]; b = mt*16+(lane>>2)+8*(reg&1),
//              k = k8*8+(lane&3)+4*(reg>>1)
__global__ void prep_kernel(
    const float* __restrict__ x,
    const float* __restrict__ Wxf, const float* __restrict__ Whf, const float* __restrict__ bhf,
    const float* __restrict__ Wxi, const float* __restrict__ Whi, const float* __restrict__ bhi,
    const float* __restrict__ Wxc, const float* __restrict__ Whc, const float* __restrict__ bhc,
    const float* __restrict__ Wxo, const float* __restrict__ Who, const float* __restrict__ bho)
{
    const float* Wx[4] = {Wxf, Wxi, Wxc, Wxo};
    const float* Wh[4] = {Whf, Whi, Whc, Who};
    const float* bh[4] = {bhf, bhi, bhc, bho};

    size_t gid = (size_t)blockIdx.x * blockDim.x + threadIdx.x;
    size_t str = (size_t)gridDim.x * blockDim.x;

    for (size_t i = gid; i < (size_t)G4 * KTOT; i += str) {
        int j = (int)(i / KTOT), k = (int)(i % KTOT);
        int g = (j >> 3) & 3;
        int r = (j >> 5) * 8 + (j & 7);
        float v = (k < IN) ? Wx[g][(size_t)r * IN + k]
                           : Wh[g][(size_t)r * HID + (k - IN)];
        d_W[i] = tf32r(v);
    }
    for (size_t i = gid; i < (size_t)G4; i += str) {
        int g = (int)((i >> 3) & 3);
        int r = (int)((i >> 5) * 8 + (i & 7));
        d_bias[i] = bh[g][r];
    }
    for (size_t i = gid; i < (size_t)SEQT * K8X * 4 * 32 * 4; i += str) {
        int r    = (int)(i & 3);
        int lane = (int)((i >> 2) & 31);
        int mt   = (int)((i >> 7) & 3);
        int k8   = (int)((i >> 9) & 63);
        int t    = (int)(i >> 15);
        int b = mt * 16 + (lane >> 2) + 8 * (r & 1);
        int k = k8 * 8 + (lane & 3) + 4 * (r >> 1);
        d_xfrag[i] = tf32r(x[((size_t)b * SEQT + t) * IN + k]);
    }
    for (size_t i = gid; i < (size_t)2 * 128 * 4 * 32 * 4; i += str)
        d_hfrag[i] = 0.f;
    for (size_t i = gid; i < 8 * 64; i += str) d_bar_grp[i] = 0u;
    if (gid == 0) d_bar_root = 0u;
}

// ============================ two-level grid barrier ========================
__device__ __forceinline__ void grid_bar(int t, int blk)
{
    __syncthreads();
    if (threadIdx.x == 0) {
        __threadfence();
        const unsigned g = (unsigned)(blk >> 4);              // 8 groups of 16
        unsigned v = atomicAdd(&d_bar_grp[g * 64], 1u) + 1u;
        if (v == 16u * (unsigned)(t + 1))
            atomicAdd(&d_bar_root, 1u);
        while (*(volatile unsigned*)&d_bar_root < 8u * (unsigned)(t + 1))
            __nanosleep(32);
        __threadfence();
    }
    __syncthreads();
}

// A-fragment load: one LDG.128, coalesced across the warp
__device__ __forceinline__ uint4 ldA(int t, int rbuf, int k8, int mt, int lane)
{
    if (k8 < K8X) {
        size_t off = ((((size_t)t * K8X + k8) * 4 + mt) * 32 + lane) * 4;
        return __ldg((const uint4*)&d_xfrag[off]);
    } else {
        size_t off = (((size_t)(rbuf * 128 + (k8 - K8X)) * 4 + mt) * 32 + lane) * 4;
        return __ldcg((const uint4*)&d_hfrag[off]);
    }
}

// ============================ main persistent kernel ========================
__global__ void __launch_bounds__(NTHR, 1) lstm_kernel(
    const float* __restrict__ Wout,
    const float* __restrict__ bout,
    float* __restrict__ out)
{
    extern __shared__ float smf[];
    float* Wf = smf;                 // fragment-packed weights
    float* P  = smf + WF_FLOATS;     // 8 merged partial tiles

    const int tid  = threadIdx.x;
    const int wid  = tid >> 5;
    const int lane = tid & 31;
    const int g8   = lane >> 2;
    const int ql   = lane & 3;
    const int blk  = blockIdx.x;

    const int kslice = wid >> 1;          // 0..7
    const int mhalf  = wid & 1;           // batch half
    const int k8base = kslice * KSL;
    const int mbase  = mhalf * 2;         // mt in {mbase, mbase+1}

    // ---- one-time: pack this CTA's W columns into fragment order ----
    for (int j = tid; j < K8TOT * 4 * 32; j += NTHR) {
        int k8 = j >> 7, nt = (j >> 5) & 3, ln = j & 31;
        size_t col = (size_t)(blk * 32 + nt * 8 + (ln >> 2));
        int k = k8 * 8 + (ln & 3);
        Wf[j * 2 + 0] = __ldg(&d_W[col * KTOT + k]);
        Wf[j * 2 + 1] = __ldg(&d_W[col * KTOT + k + 4]);
    }
    __syncthreads();

    // ---- epilogue persistent state: each thread owns ONE (b,u) pair ----
    const int bp = tid >> 3, up = tid & 7;
    float cst = 0.f;
    float bias[4];
#pragma unroll
    for (int g = 0; g < 4; g++)
        bias[g] = __ldg(&d_bias[blk * 32 + g * 8 + up]);

    for (int t = 0; t < SEQT; t++) {
        const int rbuf = t & 1, wbuf = rbuf ^ 1;

        // -------- MMA phase: M=32 x N=32, K=192 per warp, no syncs ---------
        float acc[2][4][4];
#pragma unroll
        for (int m2 = 0; m2 < 2; m2++)
#pragma unroll
            for (int nt = 0; nt < 4; nt++)
#pragma unroll
                for (int c = 0; c < 4; c++) acc[m2][nt][c] = 0.f;

        uint4 apf[3][2];
#pragma unroll
        for (int d = 0; d < 3; d++)
#pragma unroll
            for (int m2 = 0; m2 < 2; m2++)
                apf[d][m2] = ldA(t, rbuf, k8base + d, mbase + m2, lane);

#pragma unroll 3
        for (int j = 0; j < KSL; j++) {
            const int slot = j % 3;
            uint32_t bfr[4][2];
#pragma unroll
            for (int nt = 0; nt < 4; nt++) {
                float2 bv = *(const float2*)
                    &Wf[(((k8base + j) * 4) + nt) * 64 + lane * 2];
                bfr[nt][0] = __float_as_uint(bv.x);
                bfr[nt][1] = __float_as_uint(bv.y);
            }
#pragma unroll
            for (int m2 = 0; m2 < 2; m2++)
#pragma unroll
                for (int nt = 0; nt < 4; nt++)
                    mma_tf32(acc[m2][nt], (const uint32_t*)&apf[slot][m2], bfr[nt]);
            if (j + 3 < KSL) {
#pragma unroll
                for (int m2 = 0; m2 < 2; m2++)
                    apf[slot][m2] = ldA(t, rbuf, k8base + j + 3, mbase + m2, lane);
            }
        }

        // -------- two-phase partial merge into 8 tiles --------
        // tile index = (kslice & 3) * 2 + mhalf == wid & 7
        float* Pw = P + (wid & 7) * P_TILE;
        if (wid < 8) {
#pragma unroll
            for (int m2 = 0; m2 < 2; m2++)
#pragma unroll
                for (int nt = 0; nt < 4; nt++)
#pragma unroll
                    for (int c = 0; c < 4; c++) {
                        int row = m2 * 16 + g8 + 8 * (c >> 1);
                        int col = nt * 8 + 2 * ql + (c & 1);
                        Pw[row * P_PITCH + col] = acc[m2][nt][c];
                    }
        }
        __syncthreads();
        if (wid >= 8) {
#pragma unroll
            for (int m2 = 0; m2 < 2; m2++)
#pragma unroll
                for (int nt = 0; nt < 4; nt++)
#pragma unroll
                    for (int c = 0; c < 4; c++) {
                        int row = m2 * 16 + g8 + 8 * (c >> 1);
                        int col = nt * 8 + 2 * ql + (c & 1);
                        Pw[row * P_PITCH + col] += acc[m2][nt][c];
                    }
        }
        __syncthreads();

        // -------- reduction + gate fusion (1 pair per thread) --------
        {
            const int mh = bp >> 5, r = bp & 31;
            float pa[4];
#pragma unroll
            for (int g = 0; g < 4; g++) {
                float s = bias[g];
#pragma unroll
                for (int ks = 0; ks < 4; ks++)
                    s += P[(ks * 2 + mh) * P_TILE + r * P_PITCH + g * 8 + up];
                pa[g] = s;
            }
            float f = sigf(pa[0]), ig = sigf(pa[1]);
            float ch = tanhfast(pa[2]), o = sigf(pa[3]);
            cst = f * cst + ig * ch;
            float hv = tf32r(o * tanhfast(cst));
            int ug = blk * 8 + up;
            if (t < SEQT - 1) {
                int hidx = ug >> 3;
                int mtw  = bp >> 4;
                int lw   = (bp & 7) * 4 + (ug & 3);
                int rw   = 2 * ((ug >> 2) & 1) + ((bp >> 3) & 1);
                __stcg(&d_hfrag[(((size_t)(wbuf * 128 + hidx) * 4 + mtw) * 32 + lw) * 4 + rw], hv);
            } else {
                d_hfin[bp * HID + ug] = hv;
            }
        }

        grid_bar(t, blk);
    }

    // ---- tail: out[b][o] = h_final[b] . Wout[o] + bout[o]
    if (tid < 256) {
        const int gtid = blk * 256 + tid;           // 0..32767 == BATCH*OUTD
        const int b = gtid & 63, o = gtid >> 6;
        const float4* hr = (const float4*)&d_hfin[(size_t)b * HID];
        const float4* wr = (const float4*)(Wout + ((size_t)o << 10));
        float s = __ldg(&bout[o]);
#pragma unroll 4
        for (int k = 0; k < HID / 4; k++) {
            float4 h4 = __ldcg(hr + k);
            float4 w4 = __ldg(wr + k);
            s += h4.x * w4.x + h4.y * w4.y + h4.z * w4.z + h4.w * w4.w;
        }
        out[(size_t)b * OUTD + o] = s;
    }
}

// ============================================================================
extern "C" void kernel_launch(void* const* d_in, const int* in_sizes, int n_in,
                              void* d_out, int out_size)
{
    (void)in_sizes; (void)n_in; (void)out_size;
    const float* x    = (const float*)d_in[0];
    const float* Wxf  = (const float*)d_in[1];
    const float* Whf  = (const float*)d_in[2];
    const float* bhf  = (const float*)d_in[3];
    const float* Wxi  = (const float*)d_in[4];
    const float* Whi  = (const float*)d_in[5];
    const float* bhi  = (const float*)d_in[6];
    const float* Wxc  = (const float*)d_in[7];
    const float* Whc  = (const float*)d_in[8];
    const float* bhc  = (const float*)d_in[9];
    const float* Wxo  = (const float*)d_in[10];
    const float* Who  = (const float*)d_in[11];
    const float* bho  = (const float*)d_in[12];
    const float* Wout = (const float*)d_in[13];
    const float* bout = (const float*)d_in[14];
    float* out = (float*)d_out;

    cudaFuncSetAttribute(lstm_kernel,
                         cudaFuncAttributeMaxDynamicSharedMemorySize, SMEM_TOTAL);

    prep_kernel<<<2048, 256>>>(x, Wxf, Whf, bhf, Wxi, Whi, bhi,
                               Wxc, Whc, bhc, Wxo, Who, bho);
    lstm_kernel<<<NBLK, NTHR, SMEM_TOTAL>>>(Wout, bout, out);
}